// round 10
// baseline (speedup 1.0000x reference)
#include <cuda_runtime.h>
#include <cuda_fp16.h>
#include <cstdint>
#include <math.h>

// Problem constants
#define BB 8
#define LL 8192
#define CC 512
#define HH 8
#define WS 32
#define SHIFT 16
#define MLPD 2048
#define NW (LL / WS)
#define NTOK (BB * LL)
#define HD (CC / HH)

// ---------------- scratch (device globals; allocation-free) ----------------
__device__ __half g_h   [(size_t)NTOK * CC];
__device__ __half g_qkv [(size_t)NTOK * 3 * CC];
__device__ __half g_att [(size_t)NTOK * CC];
__device__ float  g_y   [(size_t)NTOK * CC];
__device__ __half g_h2  [(size_t)NTOK * CC];
__device__ __half g_mid [(size_t)NTOK * MLPD];
__device__ __half g_wq  [3 * CC * CC];
__device__ __half g_wo  [CC * CC];
__device__ __half g_w1  [MLPD * CC];
__device__ __half g_w2  [CC * MLPD];

// ---------------- f32x2 helpers (SASS FFMA2; PTX-only path) ----------------
__device__ __forceinline__ unsigned long long pk2(float a, float b) {
    unsigned long long r;
    asm("mov.b64 %0, {%1, %2};" : "=l"(r) : "f"(a), "f"(b));
    return r;
}
__device__ __forceinline__ void upk2(unsigned long long p, float& a, float& b) {
    asm("mov.b64 {%0, %1}, %2;" : "=f"(a), "=f"(b) : "l"(p));
}
__device__ __forceinline__ unsigned long long ffma2(
    unsigned long long a, unsigned long long b, unsigned long long c) {
    unsigned long long d;
    asm("fma.rn.f32x2 %0, %1, %2, %3;" : "=l"(d) : "l"(a), "l"(b), "l"(c));
    return d;
}

// ---------------- fused weight conversion (all 4 weights, one launch) -------
// float4 ranges: qkv 196608 | wo 65536 | w1 262144 | w2 262144  (total 786432)
__global__ __launch_bounds__(256) void f2h_all_kernel(
    const float* __restrict__ w_qkv, const float* __restrict__ w_out,
    const float* __restrict__ w_fc1, const float* __restrict__ w_fc2,
    __half* __restrict__ wq, __half* __restrict__ wo,
    __half* __restrict__ w1, __half* __restrict__ w2)
{
    int i = blockIdx.x * blockDim.x + threadIdx.x;
    const float* src; __half* dst; int off;
    if (i < 196608)      { src = w_qkv; dst = wq; off = i; }
    else if (i < 262144) { src = w_out; dst = wo; off = i - 196608; }
    else if (i < 524288) { src = w_fc1; dst = w1; off = i - 262144; }
    else                 { src = w_fc2; dst = w2; off = i - 524288; }
    float4 v = reinterpret_cast<const float4*>(src)[off];
    reinterpret_cast<__half2*>(dst)[2 * off]     = __floats2half2_rn(v.x, v.y);
    reinterpret_cast<__half2*>(dst)[2 * off + 1] = __floats2half2_rn(v.z, v.w);
}

// ---------------- LayerNorm (fp32 in, half out; optional roll) --------------
__global__ __launch_bounds__(128) void ln_kernel(
    const float* __restrict__ in, const float* __restrict__ g,
    const float* __restrict__ be, __half* __restrict__ out, int rolled)
{
    int row = blockIdx.x;
    int b   = row >> 13;
    int l   = row & (LL - 1);
    int lsrc = rolled ? ((l + SHIFT) & (LL - 1)) : l;
    const float* src = in + ((size_t)((b << 13) | lsrc)) * CC;

    int tid = threadIdx.x;
    float4 v = reinterpret_cast<const float4*>(src)[tid];
    float s1 = v.x + v.y + v.z + v.w;
    float s2 = v.x*v.x + v.y*v.y + v.z*v.z + v.w*v.w;
    #pragma unroll
    for (int off = 16; off > 0; off >>= 1) {
        s1 += __shfl_down_sync(0xffffffffu, s1, off);
        s2 += __shfl_down_sync(0xffffffffu, s2, off);
    }
    __shared__ float sh1[4], sh2[4];
    int wid = tid >> 5, lane = tid & 31;
    if (lane == 0) { sh1[wid] = s1; sh2[wid] = s2; }
    __syncthreads();
    float t1 = sh1[0] + sh1[1] + sh1[2] + sh1[3];
    float t2 = sh2[0] + sh2[1] + sh2[2] + sh2[3];
    float mean = t1 * (1.0f / CC);
    float var  = t2 * (1.0f / CC) - mean * mean;
    float inv  = rsqrtf(var + 1e-5f);

    float4 gg = reinterpret_cast<const float4*>(g)[tid];
    float4 bb = reinterpret_cast<const float4*>(be)[tid];
    __half2* dst = reinterpret_cast<__half2*>(out + (size_t)row * CC);
    dst[2 * tid]     = __floats2half2_rn((v.x - mean) * inv * gg.x + bb.x,
                                         (v.y - mean) * inv * gg.y + bb.y);
    dst[2 * tid + 1] = __floats2half2_rn((v.z - mean) * inv * gg.z + bb.z,
                                         (v.w - mean) * inv * gg.w + bb.w);
}

// ---------------- windowed double-softmax attention (f32x2 math) ------------
// grid = (B*nW, HH/4), block = 128. Warp w handles head blockIdx.y*4 + w.
#define ATT_SLICE (3 * WS * HD + 64)          // floats per warp slice
#define ATT_SMEM  (4 * ATT_SLICE * 4)         // bytes

__global__ __launch_bounds__(128) void attn_kernel(
    const __half* __restrict__ qkv, const float* __restrict__ rel_table,
    __half* __restrict__ out)
{
    extern __shared__ float smf[];
    int w   = blockIdx.x;
    int wid = threadIdx.x >> 5;
    int x   = threadIdx.x & 31;
    int h   = blockIdx.y * 4 + wid;

    float* qs  = smf + wid * ATT_SLICE;       // [WS][HD]
    float* ks  = qs + WS * HD;
    float* vs  = ks + WS * HD;
    float* rel = vs + WS * HD;

    const __half* base = qkv + (size_t)w * WS * (3 * CC) + h * HD;
    #pragma unroll 4
    for (int y = 0; y < WS; ++y) {
        const __half2* qrow = reinterpret_cast<const __half2*>(base + (size_t)y * 3 * CC);
        const __half2* krow = reinterpret_cast<const __half2*>(base + (size_t)y * 3 * CC + CC);
        const __half2* vrow = reinterpret_cast<const __half2*>(base + (size_t)y * 3 * CC + 2 * CC);
        float2 q = __half22float2(qrow[x]);
        float2 k = __half22float2(krow[x]);
        float2 vv = __half22float2(vrow[x]);
        qs[y * HD + 2 * x] = q.x;  qs[y * HD + 2 * x + 1] = q.y;
        ks[y * HD + 2 * x] = k.x;  ks[y * HD + 2 * x + 1] = k.y;
        vs[y * HD + 2 * x] = vv.x; vs[y * HD + 2 * x + 1] = vv.y;
    }
    if (x < 2 * WS - 1) rel[x] = rel_table[x * HH + h];
    if (x + 32 < 2 * WS - 1) rel[x + 32] = rel_table[(x + 32) * HH + h];
    __syncwarp();

    // preload q row (packed f32 pairs)
    ulonglong2 qr[16];
    const ulonglong2* qx = reinterpret_cast<const ulonglong2*>(qs + x * HD);
    #pragma unroll
    for (int i = 0; i < 16; ++i) qr[i] = qx[i];

    const float scale = 0.125f;
    float s[WS];
    #pragma unroll 4
    for (int y = 0; y < WS; ++y) {
        const ulonglong2* ky = reinterpret_cast<const ulonglong2*>(ks + y * HD);
        unsigned long long a0 = 0ull, a1 = 0ull, a2 = 0ull, a3 = 0ull;
        #pragma unroll
        for (int i = 0; i < 16; i += 2) {
            ulonglong2 k0 = ky[i], k1 = ky[i + 1];
            a0 = ffma2(qr[i].x,     k0.x, a0);
            a1 = ffma2(qr[i].y,     k0.y, a1);
            a2 = ffma2(qr[i + 1].x, k1.x, a2);
            a3 = ffma2(qr[i + 1].y, k1.y, a3);
        }
        float f0, f1, f2, f3, f4, f5, f6, f7;
        upk2(a0, f0, f1); upk2(a1, f2, f3);
        upk2(a2, f4, f5); upk2(a3, f6, f7);
        s[y] = ((f0 + f1) + (f2 + f3) + ((f4 + f5) + (f6 + f7))) * scale;
    }

    // softmax #1
    float mx = -1e30f;
    #pragma unroll
    for (int y = 0; y < WS; ++y) mx = fmaxf(mx, s[y]);
    float sum = 0.f;
    #pragma unroll
    for (int y = 0; y < WS; ++y) { s[y] = __expf(s[y] - mx); sum += s[y]; }
    float isum = 1.0f / sum;
    // + rel bias + shift mask, softmax #2
    int wi = w & (NW - 1);
    bool lastw = (wi == NW - 1);
    int px = wi * WS + x;
    int segx = (px >= LL - SHIFT) ? 2 : ((px >= LL - WS) ? 1 : 0);
    #pragma unroll
    for (int y = 0; y < WS; ++y) {
        float t = s[y] * isum + rel[x - y + WS - 1];
        if (lastw) {
            int py = wi * WS + y;
            int segy = (py >= LL - SHIFT) ? 2 : ((py >= LL - WS) ? 1 : 0);
            if (segy != segx) t -= 100.0f;
        }
        s[y] = t;
    }
    mx = -1e30f;
    #pragma unroll
    for (int y = 0; y < WS; ++y) mx = fmaxf(mx, s[y]);
    sum = 0.f;
    #pragma unroll
    for (int y = 0; y < WS; ++y) { s[y] = __expf(s[y] - mx); sum += s[y]; }
    isum = 1.0f / sum;

    // o[x,:] = att @ v  (packed accumulators)
    unsigned long long o[32];
    #pragma unroll
    for (int i = 0; i < 32; ++i) o[i] = 0ull;
    #pragma unroll 4
    for (int y = 0; y < WS; ++y) {
        float a = s[y] * isum;
        unsigned long long ap = pk2(a, a);
        const ulonglong2* vy = reinterpret_cast<const ulonglong2*>(vs + y * HD);
        #pragma unroll
        for (int i = 0; i < 16; ++i) {
            ulonglong2 vv = vy[i];
            o[2 * i]     = ffma2(ap, vv.x, o[2 * i]);
            o[2 * i + 1] = ffma2(ap, vv.y, o[2 * i + 1]);
        }
    }
    __half2* orow = reinterpret_cast<__half2*>(
        out + (size_t)(w * WS + x) * CC + h * HD);
    #pragma unroll
    for (int j = 0; j < 32; ++j) {
        float fa, fb;
        upk2(o[j], fa, fb);
        orow[j] = __floats2half2_rn(fa, fb);
    }
}

// ---------------- fp16 tensor-core GEMM NT ----------------------------------
// Block 128x128, 8 warps (2x4), warp tile 64x32, K-stage 32 halves,
// 4-stage cp.async ring, ONE __syncthreads per stage.
#define EPI_NONE 0
#define EPI_ATTN 1
#define EPI_GELU 2
#define EPI_RES  3

#define KCH 32
#define SROW 40
#define NSTG 4
#define STGH (128 * SROW)
#define STAGE_H (2 * STGH)
#define HG_SMEM (NSTG * STAGE_H * 2)

template <int EPI>
__global__ __launch_bounds__(256) void hgemm(
    const __half* __restrict__ A, const __half* __restrict__ W,
    const float* __restrict__ bias, void* __restrict__ outv,
    const float* __restrict__ extra, int M, int N, int K)
{
    extern __shared__ __half sm[];

    const int tid  = threadIdx.x;
    const int lane = tid & 31;
    const int warp = tid >> 5;
    const int wm = warp >> 2, wn = warp & 3;
    const int bm = blockIdx.y * 128, bn = blockIdx.x * 128;

    const int lr = tid >> 1;
    const int lc = (tid & 1) * 16;
    const __half* gA = A + (size_t)(bm + lr) * K + lc;
    const __half* gB = W + (size_t)(bn + lr) * K + lc;

    const uint32_t sbase = (uint32_t)__cvta_generic_to_shared(sm);
    const uint32_t dst0  = (uint32_t)(lr * SROW + lc) * 2;

    const int rr  = lane & 7, grp = lane >> 3;
    const int mr = (grp & 1) * 8;
    const int kc = (grp >> 1) * 8;
    uint32_t aoff[4], boff[2];
    #pragma unroll
    for (int mt = 0; mt < 4; ++mt)
        aoff[mt] = (uint32_t)(((wm * 64 + mt * 16 + mr + rr) * SROW + kc) * 2);
    #pragma unroll
    for (int np = 0; np < 2; ++np)
        boff[np] = (uint32_t)(((wn * 32 + np * 16 + mr + rr) * SROW + kc) * 2);

    float c[4][4][4];
    #pragma unroll
    for (int i = 0; i < 4; ++i)
        #pragma unroll
        for (int j = 0; j < 4; ++j)
            #pragma unroll
            for (int r = 0; r < 4; ++r) c[i][j][r] = 0.f;

    const int S = K / KCH;

    auto issue = [&](int t) {
        uint32_t base = sbase + (uint32_t)(t & (NSTG - 1)) * STAGE_H * 2;
        uint32_t da = base + dst0;
        uint32_t db = base + STGH * 2 + dst0;
        const __half* ga = gA + (size_t)t * KCH;
        const __half* gb = gB + (size_t)t * KCH;
        asm volatile("cp.async.cg.shared.global [%0], [%1], 16;" :: "r"(da),      "l"(ga));
        asm volatile("cp.async.cg.shared.global [%0], [%1], 16;" :: "r"(da + 16), "l"(ga + 8));
        asm volatile("cp.async.cg.shared.global [%0], [%1], 16;" :: "r"(db),      "l"(gb));
        asm volatile("cp.async.cg.shared.global [%0], [%1], 16;" :: "r"(db + 16), "l"(gb + 8));
    };

    issue(0); asm volatile("cp.async.commit_group;");
    issue(1); asm volatile("cp.async.commit_group;");
    issue(2); asm volatile("cp.async.commit_group;");

    for (int s = 0; s < S; ++s) {
        asm volatile("cp.async.wait_group 2;");
        __syncthreads();
        int t = s + 3;
        if (t < S) issue(t);
        asm volatile("cp.async.commit_group;");

        const uint32_t base = sbase + (uint32_t)(s & (NSTG - 1)) * STAGE_H * 2;
        const uint32_t ab = base;
        const uint32_t bb = base + STGH * 2;
        #pragma unroll
        for (int kk = 0; kk < 2; ++kk) {
            uint32_t a[4][4], b2[2][4];
            #pragma unroll
            for (int mt = 0; mt < 4; ++mt) {
                asm volatile("ldmatrix.sync.aligned.m8n8.x4.shared.b16 {%0,%1,%2,%3}, [%4];"
                    : "=r"(a[mt][0]), "=r"(a[mt][1]), "=r"(a[mt][2]), "=r"(a[mt][3])
                    : "r"(ab + aoff[mt] + kk * 32));
            }
            #pragma unroll
            for (int np = 0; np < 2; ++np) {
                asm volatile("ldmatrix.sync.aligned.m8n8.x4.shared.b16 {%0,%1,%2,%3}, [%4];"
                    : "=r"(b2[np][0]), "=r"(b2[np][1]), "=r"(b2[np][2]), "=r"(b2[np][3])
                    : "r"(bb + boff[np] + kk * 32));
            }
            #pragma unroll
            for (int mt = 0; mt < 4; ++mt) {
                #pragma unroll
                for (int nt = 0; nt < 4; ++nt) {
                    asm volatile(
                        "mma.sync.aligned.m16n8k16.row.col.f32.f16.f16.f32 "
                        "{%0,%1,%2,%3}, {%4,%5,%6,%7}, {%8,%9}, {%0,%1,%2,%3};"
                        : "+f"(c[mt][nt][0]), "+f"(c[mt][nt][1]),
                          "+f"(c[mt][nt][2]), "+f"(c[mt][nt][3])
                        : "r"(a[mt][0]), "r"(a[mt][1]), "r"(a[mt][2]), "r"(a[mt][3]),
                          "r"(b2[nt >> 1][nt & 1]), "r"(b2[nt >> 1][2 + (nt & 1)]));
                }
            }
        }
    }

    // ---------------- epilogue ----------------
    const int mrow = lane >> 2;
    const int ncol = (lane & 3) * 2;
    #pragma unroll
    for (int mt = 0; mt < 4; ++mt) {
        #pragma unroll
        for (int half = 0; half < 2; ++half) {
            int m = bm + wm * 64 + mt * 16 + mrow + half * 8;
            #pragma unroll
            for (int nt = 0; nt < 4; ++nt) {
                int n = bn + wn * 32 + nt * 8 + ncol;
                float v0 = c[mt][nt][half * 2 + 0];
                float v1 = c[mt][nt][half * 2 + 1];
                if (EPI == EPI_NONE) {
                    __half* out = (__half*)outv;
                    __stcs(reinterpret_cast<__half2*>(out + (size_t)m * N + n),
                           __floats2half2_rn(v0, v1));
                } else if (EPI == EPI_ATTN) {
                    float* out = (float*)outv;
                    int b = m >> 13;
                    int l = ((m & (LL - 1)) + SHIFT) & (LL - 1);
                    size_t idx = ((size_t)((b << 13) | l)) * CC + n;
                    float2 xr = *reinterpret_cast<const float2*>(extra + idx);
                    float2 br = *reinterpret_cast<const float2*>(bias + n);
                    *reinterpret_cast<float2*>(out + idx) =
                        make_float2(xr.x + v0 + br.x, xr.y + v1 + br.y);
                } else if (EPI == EPI_GELU) {
                    __half* out = (__half*)outv;
                    float2 br = *reinterpret_cast<const float2*>(bias + n);
                    float a0 = v0 + br.x, a1 = v1 + br.y;
                    float g0 = 0.5f * a0 * (1.0f + erff(a0 * 0.70710678118654752f));
                    float g1 = 0.5f * a1 * (1.0f + erff(a1 * 0.70710678118654752f));
                    __stcs(reinterpret_cast<__half2*>(out + (size_t)m * N + n),
                           __floats2half2_rn(g0, g1));
                } else { // EPI_RES
                    float* out = (float*)outv;
                    size_t idx = (size_t)m * N + n;
                    float2 yr = *reinterpret_cast<const float2*>(extra + idx);
                    float2 br = *reinterpret_cast<const float2*>(bias + n);
                    *reinterpret_cast<float2*>(out + idx) =
                        make_float2(yr.x + v0 + br.x, yr.y + v1 + br.y);
                }
            }
        }
    }
}

// ---------------- launch ----------------------------------------------------
extern "C" void kernel_launch(void* const* d_in, const int* in_sizes, int n_in,
                              void* d_out, int out_size)
{
    const float* x      = (const float*)d_in[0];
    const float* w_qkv  = (const float*)d_in[1];
    const float* w_out  = (const float*)d_in[2];
    const float* b_out  = (const float*)d_in[3];
    const float* rel_tb = (const float*)d_in[4];
    const float* g1     = (const float*)d_in[5];
    const float* be1    = (const float*)d_in[6];
    const float* g2     = (const float*)d_in[7];
    const float* be2    = (const float*)d_in[8];
    const float* w_fc1  = (const float*)d_in[9];
    const float* b_fc1  = (const float*)d_in[10];
    const float* w_fc2  = (const float*)d_in[11];
    const float* b_fc2  = (const float*)d_in[12];
    float* out = (float*)d_out;

    __half *h, *qkv, *att, *h2, *mid, *wq, *wo, *w1, *w2;
    float *y;
    cudaGetSymbolAddress((void**)&h,   g_h);
    cudaGetSymbolAddress((void**)&qkv, g_qkv);
    cudaGetSymbolAddress((void**)&att, g_att);
    cudaGetSymbolAddress((void**)&y,   g_y);
    cudaGetSymbolAddress((void**)&h2,  g_h2);
    cudaGetSymbolAddress((void**)&mid, g_mid);
    cudaGetSymbolAddress((void**)&wq,  g_wq);
    cudaGetSymbolAddress((void**)&wo,  g_wo);
    cudaGetSymbolAddress((void**)&w1,  g_w1);
    cudaGetSymbolAddress((void**)&w2,  g_w2);

    cudaFuncSetAttribute(hgemm<EPI_NONE>, cudaFuncAttributeMaxDynamicSharedMemorySize, HG_SMEM);
    cudaFuncSetAttribute(hgemm<EPI_ATTN>, cudaFuncAttributeMaxDynamicSharedMemorySize, HG_SMEM);
    cudaFuncSetAttribute(hgemm<EPI_GELU>, cudaFuncAttributeMaxDynamicSharedMemorySize, HG_SMEM);
    cudaFuncSetAttribute(hgemm<EPI_RES>,  cudaFuncAttributeMaxDynamicSharedMemorySize, HG_SMEM);
    cudaFuncSetAttribute(attn_kernel,     cudaFuncAttributeMaxDynamicSharedMemorySize, ATT_SMEM);

    // 0. fp16 weight copies (one fused launch)
    f2h_all_kernel<<<786432 / 256, 256>>>(w_qkv, w_out, w_fc1, w_fc2, wq, wo, w1, w2);

    // 1. h = half(roll(LN1(x), -SHIFT))
    ln_kernel<<<NTOK, 128>>>(x, g1, be1, h, 1);
    // 2. qkv = h @ wq^T
    hgemm<EPI_NONE><<<dim3(3 * CC / 128, NTOK / 128), 256, HG_SMEM>>>(
        h, wq, nullptr, qkv, nullptr, NTOK, 3 * CC, CC);
    // 3. windowed attention (4 heads per 128-thread block, f32x2 math)
    attn_kernel<<<dim3(BB * NW, HH / 4), 128, ATT_SMEM>>>(qkv, rel_tb, att);
    // 4. y = x + roll(att @ wo^T + b_out, +SHIFT)
    hgemm<EPI_ATTN><<<dim3(CC / 128, NTOK / 128), 256, HG_SMEM>>>(
        att, wo, b_out, y, x, NTOK, CC, CC);
    // 5. h2 = half(LN2(y))
    ln_kernel<<<NTOK, 128>>>(y, g2, be2, h2, 0);
    // 6. mid = half(gelu(h2 @ w1^T + b_fc1))
    hgemm<EPI_GELU><<<dim3(MLPD / 128, NTOK / 128), 256, HG_SMEM>>>(
        h2, w1, b_fc1, mid, nullptr, NTOK, MLPD, CC);
    // 7. out = y + mid @ w2^T + b_fc2
    hgemm<EPI_RES><<<dim3(CC / 128, NTOK / 128), 256, HG_SMEM>>>(
        mid, w2, b_fc2, out, y, NTOK, CC, MLPD);
}